// round 4
// baseline (speedup 1.0000x reference)
#include <cuda_runtime.h>
#include <stdint.h>

// BloomEmbedding: out[n, h*32 + j] = tables[h, hash(ids[n], 42+h), j]
// ids: [819200] int32, tables: [4, 1000000, 32] f32, out: [819200, 128] f32
//
// R4: MLP=8. R3 showed the kernel is bound by in-flight read bytes
// (Little's law); 4 gathers/thread got DRAM to 78%. Double to 8 independent
// front-batched LDG.128 gathers per thread. Addresses kept as uint32
// float4-element indices (max ~32M) to hold register count ~56.

#define TABLE_SIZE 1000000u
#define SEED 42u
#define IDS_PER_THREAD 8

__device__ __forceinline__ uint32_t hash_id(uint32_t id, uint32_t seed) {
    uint32_t x = id + seed;
    x ^= x >> 16;
    x *= 0x7FEB352Du;
    x ^= x >> 15;
    x *= 0x846CA68Bu;
    x ^= x >> 16;
    return x % TABLE_SIZE;
}

__global__ void __launch_bounds__(256)
bloom_embedding_kernel(const int* __restrict__ ids,
                       const float4* __restrict__ tables,
                       float4* __restrict__ out,
                       int n_ids) {
    int t = blockIdx.x * blockDim.x + threadIdx.x;
    int lane = t & 31;                   // 0..31 within the 128-float row
    int h    = lane >> 3;                // hash table 0..3
    int j    = lane & 7;                 // float4 within the 32-float sub-row
    uint32_t seed = SEED + (uint32_t)h;
    uint32_t base = (uint32_t)h * TABLE_SIZE;   // table offset in rows

    int n0 = (t >> 5) * IDS_PER_THREAD;  // first id of this group
    if (n0 >= n_ids) return;

    if (n0 + IDS_PER_THREAD <= n_ids) {
        uint32_t src[IDS_PER_THREAD];    // float4-element index, fits in u32
        #pragma unroll
        for (int k = 0; k < IDS_PER_THREAD; k++) {
            uint32_t id  = (uint32_t)__ldg(ids + n0 + k);
            uint32_t idx = hash_id(id, seed);
            src[k] = (base + idx) * 8u + (uint32_t)j;
        }
        float4 v[IDS_PER_THREAD];
        #pragma unroll
        for (int k = 0; k < IDS_PER_THREAD; k++)
            v[k] = __ldcg(tables + src[k]);      // 8 independent in-flight loads
        #pragma unroll
        for (int k = 0; k < IDS_PER_THREAD; k++)
            __stcs(out + (size_t)(n0 + k) * 32u + (size_t)lane, v[k]);
    } else {
        for (int k = 0; k < IDS_PER_THREAD && n0 + k < n_ids; k++) {
            uint32_t id  = (uint32_t)__ldg(ids + n0 + k);
            uint32_t idx = hash_id(id, seed);
            float4 v = __ldcg(tables + (size_t)(base + idx) * 8u + (size_t)j);
            __stcs(out + (size_t)(n0 + k) * 32u + (size_t)lane, v);
        }
    }
}

extern "C" void kernel_launch(void* const* d_in, const int* in_sizes, int n_in,
                              void* d_out, int out_size) {
    const int*    ids    = (const int*)d_in[0];
    const float4* tables = (const float4*)d_in[1];
    float4*       out    = (float4*)d_out;

    int n_ids = in_sizes[0];             // 819200
    long long total = ((long long)n_ids + IDS_PER_THREAD - 1) / IDS_PER_THREAD * 32;
    int threads = 256;
    int blocks = (int)((total + threads - 1) / threads);
    bloom_embedding_kernel<<<blocks, threads>>>(ids, tables, out, n_ids);
}

// round 5
// speedup vs baseline: 1.0025x; 1.0025x over previous
#include <cuda_runtime.h>
#include <stdint.h>

// BloomEmbedding: out[n, h*32 + j] = tables[h, hash(ids[n], 42+h), j]
// ids: [819200] int32, tables: [4, 1000000, 32] f32, out: [819200, 128] f32
//
// R5: plateau confirmed at ~6.2 TB/s DRAM (mixed random-128B reads +
// streaming writes); traffic is within ~5% of the structural floor
// (419 MB writes + ~286 MB distinct gather lines + L2-window repeat misses).
// Keep the MLP=4 front-batched gather shape (16 lines in flight per warp,
// comfortably above the ~110/SM Little's-law requirement), minimize register
// cost (uint32 element indices), and run 512-thread blocks for max occupancy.

#define TABLE_SIZE 1000000u
#define SEED 42u
#define IDS_PER_THREAD 4

__device__ __forceinline__ uint32_t hash_id(uint32_t id, uint32_t seed) {
    uint32_t x = id + seed;
    x ^= x >> 16;
    x *= 0x7FEB352Du;
    x ^= x >> 15;
    x *= 0x846CA68Bu;
    x ^= x >> 16;
    return x % TABLE_SIZE;
}

__global__ void __launch_bounds__(512)
bloom_embedding_kernel(const int* __restrict__ ids,
                       const float4* __restrict__ tables,
                       float4* __restrict__ out,
                       int n_ids) {
    int t = blockIdx.x * blockDim.x + threadIdx.x;
    int lane = t & 31;                   // 0..31 within the 128-float row
    int h    = lane >> 3;                // hash table 0..3
    int j    = lane & 7;                 // float4 within the 32-float sub-row
    uint32_t seed = SEED + (uint32_t)h;
    uint32_t base = (uint32_t)h * TABLE_SIZE;   // table offset in rows

    int n0 = (t >> 5) * IDS_PER_THREAD;  // first id of this group
    if (n0 >= n_ids) return;

    if (n0 + IDS_PER_THREAD <= n_ids) {
        uint32_t src[IDS_PER_THREAD];    // float4-element index (max ~32M)
        #pragma unroll
        for (int k = 0; k < IDS_PER_THREAD; k++) {
            uint32_t id  = (uint32_t)__ldg(ids + n0 + k);
            uint32_t idx = hash_id(id, seed);
            src[k] = (base + idx) * 8u + (uint32_t)j;
        }
        float4 v[IDS_PER_THREAD];
        #pragma unroll
        for (int k = 0; k < IDS_PER_THREAD; k++)
            v[k] = __ldcg(tables + src[k]);      // 4 independent in-flight loads
        #pragma unroll
        for (int k = 0; k < IDS_PER_THREAD; k++)
            __stcs(out + (size_t)(n0 + k) * 32u + (size_t)lane, v[k]);
    } else {
        for (int k = 0; k < IDS_PER_THREAD && n0 + k < n_ids; k++) {
            uint32_t id  = (uint32_t)__ldg(ids + n0 + k);
            uint32_t idx = hash_id(id, seed);
            float4 v = __ldcg(tables + (size_t)(base + idx) * 8u + (size_t)j);
            __stcs(out + (size_t)(n0 + k) * 32u + (size_t)lane, v);
        }
    }
}

extern "C" void kernel_launch(void* const* d_in, const int* in_sizes, int n_in,
                              void* d_out, int out_size) {
    const int*    ids    = (const int*)d_in[0];
    const float4* tables = (const float4*)d_in[1];
    float4*       out    = (float4*)d_out;

    int n_ids = in_sizes[0];             // 819200
    long long total = ((long long)n_ids + IDS_PER_THREAD - 1) / IDS_PER_THREAD * 32;
    int threads = 512;
    int blocks = (int)((total + threads - 1) / threads);
    bloom_embedding_kernel<<<blocks, threads>>>(ids, tables, out, n_ids);
}

// round 6
// speedup vs baseline: 1.0574x; 1.0548x over previous
#include <cuda_runtime.h>
#include <stdint.h>

// BloomEmbedding: out[n, h*32 + j] = tables[h, hash(ids[n], 42+h), j]
// ids: [819200] int32, tables: [4, 1000000, 32] f32, out: [819200, 128] f32
//
// R6: table-phased execution. The kernel is DRAM-traffic bound; ~45 MB of
// avoidable repeat-miss traffic comes from all 4 tables (286 MB distinct-line
// footprint) competing for 126 MB of L2. Split the grid into 4 phases
// (blockIdx.y = table h, dispatched x-fastest so phases run ~sequentially);
// each phase's active footprint is 71.5 MB < L2, so intra-table hash-repeat
// accesses hit L2. Writes per (n,h) are exactly one full 128B line, stored
// evict-first (__stcs) to avoid polluting L2.

#define TABLE_SIZE 1000000u
#define SEED 42u
#define IDS_PER_THREAD 4

__device__ __forceinline__ uint32_t hash_id(uint32_t id, uint32_t seed) {
    uint32_t x = id + seed;
    x ^= x >> 16;
    x *= 0x7FEB352Du;
    x ^= x >> 15;
    x *= 0x846CA68Bu;
    x ^= x >> 16;
    return x % TABLE_SIZE;
}

__global__ void __launch_bounds__(256)
bloom_embedding_kernel(const int* __restrict__ ids,
                       const float4* __restrict__ tables,
                       float4* __restrict__ out,
                       int n_ids) {
    const int h = blockIdx.y;                    // table phase 0..3
    const uint32_t seed = SEED + (uint32_t)h;
    const uint32_t base = (uint32_t)h * TABLE_SIZE;

    int t = blockIdx.x * blockDim.x + threadIdx.x;
    int j = t & 7;                               // float4 within the 32-float sub-row
    int g = t >> 3;                              // id-group index
    int n0 = g * IDS_PER_THREAD;                 // first id of this group
    if (n0 >= n_ids) return;

    // output float4 column for this (h, j): row n is 32 float4s, table h owns
    // float4s [h*8, h*8+8) == one full 128B line per (n, h).
    const uint32_t col = (uint32_t)(h * 8 + j);

    if (n0 + IDS_PER_THREAD <= n_ids) {
        uint32_t src[IDS_PER_THREAD];            // float4-element index (max ~32M)
        #pragma unroll
        for (int k = 0; k < IDS_PER_THREAD; k++) {
            uint32_t id  = (uint32_t)__ldg(ids + n0 + k);
            uint32_t idx = hash_id(id, seed);
            src[k] = (base + idx) * 8u + (uint32_t)j;
        }
        float4 v[IDS_PER_THREAD];
        #pragma unroll
        for (int k = 0; k < IDS_PER_THREAD; k++)
            v[k] = __ldcg(tables + src[k]);      // 4 independent in-flight loads
        #pragma unroll
        for (int k = 0; k < IDS_PER_THREAD; k++)
            __stcs(out + (size_t)(n0 + k) * 32u + col, v[k]);
    } else {
        for (int k = 0; k < IDS_PER_THREAD && n0 + k < n_ids; k++) {
            uint32_t id  = (uint32_t)__ldg(ids + n0 + k);
            uint32_t idx = hash_id(id, seed);
            float4 v = __ldcg(tables + (size_t)(base + idx) * 8u + (size_t)j);
            __stcs(out + (size_t)(n0 + k) * 32u + col, v);
        }
    }
}

extern "C" void kernel_launch(void* const* d_in, const int* in_sizes, int n_in,
                              void* d_out, int out_size) {
    const int*    ids    = (const int*)d_in[0];
    const float4* tables = (const float4*)d_in[1];
    float4*       out    = (float4*)d_out;

    int n_ids = in_sizes[0];                     // 819200
    // per phase: one thread per (id-group, j): n_ids/4 groups * 8 threads
    long long per_phase = ((long long)n_ids + IDS_PER_THREAD - 1) / IDS_PER_THREAD * 8;
    int threads = 256;
    dim3 grid((unsigned)((per_phase + threads - 1) / threads), 4, 1);
    bloom_embedding_kernel<<<grid, threads>>>(ids, tables, out, n_ids);
}

// round 7
// speedup vs baseline: 1.0630x; 1.0053x over previous
#include <cuda_runtime.h>
#include <stdint.h>

// BloomEmbedding: out[n, h*32 + j] = tables[h, hash(ids[n], 42+h), j]
// ids: [819200] int32, tables: [4, 1000000, 32] f32, out: [819200, 128] f32
//
// R7: table-phased (R6, cuts ~60MB of repeat-miss DRAM traffic by keeping the
// active table footprint 71.5MB < 126MB L2) + MLP=8 (R4 showed 8 in-flight
// gathers/thread sustains ~78% DRAM even at reduced occupancy).
// Writes per (n,h) are one full 128B line, stored evict-first (__stcs).

#define TABLE_SIZE 1000000u
#define SEED 42u
#define IDS_PER_THREAD 8

__device__ __forceinline__ uint32_t hash_id(uint32_t id, uint32_t seed) {
    uint32_t x = id + seed;
    x ^= x >> 16;
    x *= 0x7FEB352Du;
    x ^= x >> 15;
    x *= 0x846CA68Bu;
    x ^= x >> 16;
    return x % TABLE_SIZE;
}

__global__ void __launch_bounds__(256)
bloom_embedding_kernel(const int* __restrict__ ids,
                       const float4* __restrict__ tables,
                       float4* __restrict__ out,
                       int n_ids) {
    const int h = blockIdx.y;                    // table phase 0..3
    const uint32_t seed = SEED + (uint32_t)h;
    const uint32_t base = (uint32_t)h * TABLE_SIZE;

    int t = blockIdx.x * blockDim.x + threadIdx.x;
    int j = t & 7;                               // float4 within the 32-float sub-row
    int g = t >> 3;                              // id-group index
    int n0 = g * IDS_PER_THREAD;                 // first id of this group
    if (n0 >= n_ids) return;

    const uint32_t col = (uint32_t)(h * 8 + j);  // out float4 column for (h, j)

    if (n0 + IDS_PER_THREAD <= n_ids) {
        uint32_t src[IDS_PER_THREAD];            // float4-element index (max ~32M)
        #pragma unroll
        for (int k = 0; k < IDS_PER_THREAD; k++) {
            uint32_t id  = (uint32_t)__ldg(ids + n0 + k);
            uint32_t idx = hash_id(id, seed);
            src[k] = (base + idx) * 8u + (uint32_t)j;
        }
        float4 v[IDS_PER_THREAD];
        #pragma unroll
        for (int k = 0; k < IDS_PER_THREAD; k++)
            v[k] = __ldcg(tables + src[k]);      // 8 independent in-flight loads
        #pragma unroll
        for (int k = 0; k < IDS_PER_THREAD; k++)
            __stcs(out + (size_t)(n0 + k) * 32u + col, v[k]);
    } else {
        for (int k = 0; k < IDS_PER_THREAD && n0 + k < n_ids; k++) {
            uint32_t id  = (uint32_t)__ldg(ids + n0 + k);
            uint32_t idx = hash_id(id, seed);
            float4 v = __ldcg(tables + (size_t)(base + idx) * 8u + (size_t)j);
            __stcs(out + (size_t)(n0 + k) * 32u + col, v);
        }
    }
}

extern "C" void kernel_launch(void* const* d_in, const int* in_sizes, int n_in,
                              void* d_out, int out_size) {
    const int*    ids    = (const int*)d_in[0];
    const float4* tables = (const float4*)d_in[1];
    float4*       out    = (float4*)d_out;

    int n_ids = in_sizes[0];                     // 819200
    // per phase: one thread per (id-group, j): n_ids/8 groups * 8 threads
    long long per_phase = ((long long)n_ids + IDS_PER_THREAD - 1) / IDS_PER_THREAD * 8;
    int threads = 256;
    dim3 grid((unsigned)((per_phase + threads - 1) / threads), 4, 1);
    bloom_embedding_kernel<<<grid, threads>>>(ids, tables, out, n_ids);
}

// round 8
// speedup vs baseline: 1.0684x; 1.0051x over previous
#include <cuda_runtime.h>
#include <stdint.h>

// BloomEmbedding: out[n, h*32 + j] = tables[h, hash(ids[n], 42+h), j]
// ids: [819200] int32, tables: [4, 1000000, 32] f32, out: [819200, 128] f32
//
// R8 (final form): table-phased + MLP=4 + vectorized id loads.
//  - blockIdx.y = table h, x-fastest dispatch => phases run ~sequentially;
//    active table footprint 71.5MB < 126MB L2 captures hash-repeat reuse
//    (cut DRAM traffic ~750 -> ~690 MB in R6).
//  - 4 independent front-batched LDG.128 gathers per thread (Little's-law
//    requirement measured satisfied at MLP>=4, occ>=60%).
//  - ids loaded as one int4 per thread (n0 is 4-aligned), broadcast across
//    the 8-thread group.
//  - __ldcg gathers (L2-only), __stcs full-128B-line output stores
//    (evict-first; output never re-read).

#define TABLE_SIZE 1000000u
#define SEED 42u
#define IDS_PER_THREAD 4

__device__ __forceinline__ uint32_t hash_id(uint32_t id, uint32_t seed) {
    uint32_t x = id + seed;
    x ^= x >> 16;
    x *= 0x7FEB352Du;
    x ^= x >> 15;
    x *= 0x846CA68Bu;
    x ^= x >> 16;
    return x % TABLE_SIZE;
}

__global__ void __launch_bounds__(256)
bloom_embedding_kernel(const int* __restrict__ ids,
                       const float4* __restrict__ tables,
                       float4* __restrict__ out,
                       int n_ids) {
    const int h = blockIdx.y;                    // table phase 0..3
    const uint32_t seed = SEED + (uint32_t)h;
    const uint32_t base = (uint32_t)h * TABLE_SIZE;

    int t = blockIdx.x * blockDim.x + threadIdx.x;
    int j = t & 7;                               // float4 within the 32-float sub-row
    int g = t >> 3;                              // id-group index
    int n0 = g * IDS_PER_THREAD;                 // first id of this group (4-aligned)
    if (n0 >= n_ids) return;

    const uint32_t col = (uint32_t)(h * 8 + j);  // out float4 column for (h, j)

    if (n0 + IDS_PER_THREAD <= n_ids) {
        // one vectorized load for the 4 ids (same address across the 8-thread
        // group -> broadcast)
        int4 id4 = __ldg((const int4*)(ids + n0));
        uint32_t idv[IDS_PER_THREAD] = {
            (uint32_t)id4.x, (uint32_t)id4.y, (uint32_t)id4.z, (uint32_t)id4.w };

        uint32_t src[IDS_PER_THREAD];            // float4-element index (max ~32M)
        #pragma unroll
        for (int k = 0; k < IDS_PER_THREAD; k++) {
            uint32_t idx = hash_id(idv[k], seed);
            src[k] = (base + idx) * 8u + (uint32_t)j;
        }
        float4 v[IDS_PER_THREAD];
        #pragma unroll
        for (int k = 0; k < IDS_PER_THREAD; k++)
            v[k] = __ldcg(tables + src[k]);      // 4 independent in-flight loads
        #pragma unroll
        for (int k = 0; k < IDS_PER_THREAD; k++)
            __stcs(out + (size_t)(n0 + k) * 32u + col, v[k]);
    } else {
        for (int k = 0; k < IDS_PER_THREAD && n0 + k < n_ids; k++) {
            uint32_t id  = (uint32_t)__ldg(ids + n0 + k);
            uint32_t idx = hash_id(id, seed);
            float4 v = __ldcg(tables + (size_t)(base + idx) * 8u + (size_t)j);
            __stcs(out + (size_t)(n0 + k) * 32u + col, v);
        }
    }
}

extern "C" void kernel_launch(void* const* d_in, const int* in_sizes, int n_in,
                              void* d_out, int out_size) {
    const int*    ids    = (const int*)d_in[0];
    const float4* tables = (const float4*)d_in[1];
    float4*       out    = (float4*)d_out;

    int n_ids = in_sizes[0];                     // 819200
    // per phase: one thread per (id-group, j): n_ids/4 groups * 8 threads
    long long per_phase = ((long long)n_ids + IDS_PER_THREAD - 1) / IDS_PER_THREAD * 8;
    int threads = 256;
    dim3 grid((unsigned)((per_phase + threads - 1) / threads), 4, 1);
    bloom_embedding_kernel<<<grid, threads>>>(ids, tables, out, n_ids);
}

// round 9
// speedup vs baseline: 1.0808x; 1.0116x over previous
#include <cuda_runtime.h>
#include <stdint.h>

// BloomEmbedding: out[n, h*32 + j] = tables[h, hash(ids[n], 42+h), j]
// ids: [819200] int32, tables: [4, 1000000, 32] f32, out: [819200, 128] f32
//
// R9: phased (traffic floor: active table footprint 71.5MB < 126MB L2
// captures hash-repeat reuse) + staggered dual 4-id batches so all 8 gather
// LDG.128s issue before the first store's scoreboard wait, sustaining the
// LSU/DRAM read queue across store drains, while register pressure stays
// below the R7 MLP=8 variant (A's address regs die before B's payload peaks).

#define TABLE_SIZE 1000000u
#define SEED 42u
#define BATCH 4
#define IDS_PER_THREAD 8   // two staggered batches of 4

__device__ __forceinline__ uint32_t hash_id(uint32_t id, uint32_t seed) {
    uint32_t x = id + seed;
    x ^= x >> 16;
    x *= 0x7FEB352Du;
    x ^= x >> 15;
    x *= 0x846CA68Bu;
    x ^= x >> 16;
    return x % TABLE_SIZE;
}

__global__ void __launch_bounds__(256)
bloom_embedding_kernel(const int* __restrict__ ids,
                       const float4* __restrict__ tables,
                       float4* __restrict__ out,
                       int n_ids) {
    const int h = blockIdx.y;                    // table phase 0..3
    const uint32_t seed = SEED + (uint32_t)h;
    const uint32_t base = (uint32_t)h * TABLE_SIZE;

    int t = blockIdx.x * blockDim.x + threadIdx.x;
    int j = t & 7;                               // float4 within the 32-float sub-row
    int g = t >> 3;                              // id-group index
    int n0 = g * IDS_PER_THREAD;                 // first id of this group (8-aligned)
    if (n0 >= n_ids) return;

    const uint32_t col = (uint32_t)(h * 8 + j);  // out float4 column for (h, j)

    if (n0 + IDS_PER_THREAD <= n_ids) {
        // ---- batch A: ids n0..n0+3 ----
        int4 idA = __ldg((const int4*)(ids + n0));
        uint32_t srcA[BATCH];
        srcA[0] = (base + hash_id((uint32_t)idA.x, seed)) * 8u + (uint32_t)j;
        srcA[1] = (base + hash_id((uint32_t)idA.y, seed)) * 8u + (uint32_t)j;
        srcA[2] = (base + hash_id((uint32_t)idA.z, seed)) * 8u + (uint32_t)j;
        srcA[3] = (base + hash_id((uint32_t)idA.w, seed)) * 8u + (uint32_t)j;
        float4 vA[BATCH];
        #pragma unroll
        for (int k = 0; k < BATCH; k++) vA[k] = __ldcg(tables + srcA[k]);

        // ---- batch B: ids n0+4..n0+7 (hash while A is in flight) ----
        int4 idB = __ldg((const int4*)(ids + n0 + 4));
        uint32_t srcB[BATCH];
        srcB[0] = (base + hash_id((uint32_t)idB.x, seed)) * 8u + (uint32_t)j;
        srcB[1] = (base + hash_id((uint32_t)idB.y, seed)) * 8u + (uint32_t)j;
        srcB[2] = (base + hash_id((uint32_t)idB.z, seed)) * 8u + (uint32_t)j;
        srcB[3] = (base + hash_id((uint32_t)idB.w, seed)) * 8u + (uint32_t)j;
        float4 vB[BATCH];
        #pragma unroll
        for (int k = 0; k < BATCH; k++) vB[k] = __ldcg(tables + srcB[k]);

        // ---- drain A, then B ----
        #pragma unroll
        for (int k = 0; k < BATCH; k++)
            __stcs(out + (size_t)(n0 + k) * 32u + col, vA[k]);
        #pragma unroll
        for (int k = 0; k < BATCH; k++)
            __stcs(out + (size_t)(n0 + 4 + k) * 32u + col, vB[k]);
    } else {
        for (int k = 0; k < IDS_PER_THREAD && n0 + k < n_ids; k++) {
            uint32_t id  = (uint32_t)__ldg(ids + n0 + k);
            uint32_t idx = hash_id(id, seed);
            float4 v = __ldcg(tables + (size_t)(base + idx) * 8u + (size_t)j);
            __stcs(out + (size_t)(n0 + k) * 32u + col, v);
        }
    }
}

extern "C" void kernel_launch(void* const* d_in, const int* in_sizes, int n_in,
                              void* d_out, int out_size) {
    const int*    ids    = (const int*)d_in[0];
    const float4* tables = (const float4*)d_in[1];
    float4*       out    = (float4*)d_out;

    int n_ids = in_sizes[0];                     // 819200
    // per phase: one thread per (8-id group, j): n_ids/8 groups * 8 threads
    long long per_phase = ((long long)n_ids + IDS_PER_THREAD - 1) / IDS_PER_THREAD * 8;
    int threads = 256;
    dim3 grid((unsigned)((per_phase + threads - 1) / threads), 4, 1);
    bloom_embedding_kernel<<<grid, threads>>>(ids, tables, out, n_ids);
}